// round 9
// baseline (speedup 1.0000x reference)
#include <cuda_runtime.h>
#include <cuda_fp16.h>
#include <cstdint>

#define B_SZ   32768
#define IN_DIM 128
#define ACT    512
#define MAXD   1024

// ---------------- device-global split arrays (h + m pieces) ----------------
__device__ __half g_prevH[(size_t)B_SZ * ACT];
__device__ __half g_prevM[(size_t)B_SZ * ACT];
__device__ __half g_inH[(size_t)B_SZ * IN_DIM];
__device__ __half g_inM[(size_t)B_SZ * IN_DIM];
__device__ __half g_wresH[ACT * ACT];
__device__ __half g_wresM[ACT * ACT];
__device__ __half g_winH[ACT * IN_DIM];
__device__ __half g_winM[ACT * IN_DIM];
__device__ __half g_wgH[3 * ACT * IN_DIM];
__device__ __half g_wgM[3 * ACT * IN_DIM];

// ---- smem byte offsets ----
// Phase A (double buffer): A tiles [128 rows][64k fp16, stride 144B] x2 pieces
//                          W tiles [64 rows][stride 144B] x2 pieces
#define PA_A(b,p)   ((b)*36864 + (p)*18432)             // 0..73728
#define PA_W(b,p)   (73728 + (b)*18432 + (p)*9216)      // 73728..110592
// Phase B (double buffer, contiguous 35840 per buffer; buffer0 disjoint from PA buffer1)
#define PB_INP(b,p) ((b)*35840 + (p)*10240)
#define PB_W(b,mt,p) ((b)*35840 + 20480 + ((mt)*2+(p))*2560)
#define LK_OFF 110592
#define TH_OFF 110848
#define SMEM_BYTES 111104

__device__ __forceinline__ void ldsm4(uint32_t r[4], uint32_t a) {
    asm volatile("ldmatrix.sync.aligned.m8n8.x4.shared.b16 {%0,%1,%2,%3}, [%4];"
        : "=r"(r[0]), "=r"(r[1]), "=r"(r[2]), "=r"(r[3]) : "r"(a));
}
__device__ __forceinline__ void ldsm4t(uint32_t r[4], uint32_t a) {
    asm volatile("ldmatrix.sync.aligned.m8n8.x4.trans.shared.b16 {%0,%1,%2,%3}, [%4];"
        : "=r"(r[0]), "=r"(r[1]), "=r"(r[2]), "=r"(r[3]) : "r"(a));
}
__device__ __forceinline__ uint32_t smem_u32(const void* p) {
    uint32_t a;
    asm("{ .reg .u64 t; cvta.to.shared.u64 t, %1; cvt.u32.u64 %0, t; }" : "=r"(a) : "l"(p));
    return a;
}
__device__ __forceinline__ void mma16(float c[4], const uint32_t a[4], uint32_t b0, uint32_t b1) {
    asm volatile("mma.sync.aligned.m16n8k16.row.col.f32.f16.f16.f32 "
        "{%0,%1,%2,%3},{%4,%5,%6,%7},{%8,%9},{%0,%1,%2,%3};"
        : "+f"(c[0]), "+f"(c[1]), "+f"(c[2]), "+f"(c[3])
        : "r"(a[0]), "r"(a[1]), "r"(a[2]), "r"(a[3]), "r"(b0), "r"(b1));
}
__device__ __forceinline__ void three(float c[4],
                                      const uint32_t ah[4], const uint32_t am[4],
                                      uint32_t bh0, uint32_t bh1, uint32_t bm0, uint32_t bm1) {
    mma16(c, ah, bh0, bh1);
    mma16(c, ah, bm0, bm1);
    mma16(c, am, bh0, bh1);
}
#define CP16(dst, src) asm volatile("cp.async.cg.shared.global [%0], [%1], 16;" :: "r"(dst), "l"(src))
#define CP_COMMIT()    asm volatile("cp.async.commit_group;" ::: "memory")
#define CP_WAIT1()     asm volatile("cp.async.wait_group 1;" ::: "memory")
#define CP_WAIT0()     asm volatile("cp.async.wait_group 0;" ::: "memory")

__device__ __forceinline__ float epi(float z, float gi_, float gf_, float go_,
                                     float p, float lk, float th) {
    float ig = 1.0f / (1.0f + expf(-gi_));
    float fg = 1.0f / (1.0f + expf(-gf_));
    float og = 1.0f / (1.0f + expf(-go_));
    float s = (1.0f - lk) * (fg * p) + lk * tanhf(ig * z);
    s *= og;
    return (s > th) ? (s - th) : s;
}

// ================= preprocess: split fp32 -> (h,m) fp16 pieces =================
__device__ __forceinline__ void do_split4(float4 v, __half* dh, __half* dm, size_t o) {
    __half h0 = __float2half_rn(v.x), h1 = __float2half_rn(v.y);
    __half h2 = __float2half_rn(v.z), h3 = __float2half_rn(v.w);
    __half m0 = __float2half_rn(v.x - __half2float(h0));
    __half m1 = __float2half_rn(v.y - __half2float(h1));
    __half m2 = __float2half_rn(v.z - __half2float(h2));
    __half m3 = __float2half_rn(v.w - __half2float(h3));
    __half2 H0 = __halves2half2(h0, h1), H1 = __halves2half2(h2, h3);
    __half2 M0 = __halves2half2(m0, m1), M1 = __halves2half2(m2, m3);
    uint2 ph, pm;
    ph.x = *reinterpret_cast<uint32_t*>(&H0); ph.y = *reinterpret_cast<uint32_t*>(&H1);
    pm.x = *reinterpret_cast<uint32_t*>(&M0); pm.y = *reinterpret_cast<uint32_t*>(&M1);
    *reinterpret_cast<uint2*>(dh + o) = ph;
    *reinterpret_cast<uint2*>(dm + o) = pm;
}

#define N0 (B_SZ * (ACT/4))        // prev      4194304
#define N1 (B_SZ * (IN_DIM/4))     // inputs    1048576
#define N2 (ACT * (ACT/4))         // wres      65536
#define N3 (ACT * (IN_DIM/4))      // win       16384
#define N4 (3*ACT * (IN_DIM/4))    // wgate     49152
#define NT (N0+N1+N2+N3+N4)

__global__ void split_all(const float* __restrict__ inputs, const float* __restrict__ prev,
                          const float* __restrict__ Wres, const float* __restrict__ Win,
                          const float* __restrict__ Wgate)
{
    for (long i = blockIdx.x * (long)blockDim.x + threadIdx.x; i < NT; i += (long)gridDim.x * blockDim.x) {
        if (i < N0) {
            long r = i >> 7, q = i & 127;      // cols4=128, sstride 1024
            float4 v = *reinterpret_cast<const float4*>(prev + r * MAXD + 4 * q);
            do_split4(v, g_prevH, g_prevM, (size_t)i * 4);
        } else if (i < N0 + N1) {
            long j = i - N0;                   // cols4=32, sstride 128
            float4 v = *reinterpret_cast<const float4*>(inputs + 4 * j);
            do_split4(v, g_inH, g_inM, (size_t)j * 4);
        } else if (i < N0 + N1 + N2) {
            long j = i - N0 - N1;
            long r = j >> 7, q = j & 127;      // cols4=128, sstride 1024
            float4 v = *reinterpret_cast<const float4*>(Wres + r * MAXD + 4 * q);
            do_split4(v, g_wresH, g_wresM, (size_t)j * 4);
        } else if (i < N0 + N1 + N2 + N3) {
            long j = i - N0 - N1 - N2;
            float4 v = *reinterpret_cast<const float4*>(Win + 4 * j);
            do_split4(v, g_winH, g_winM, (size_t)j * 4);
        } else {
            long j = i - N0 - N1 - N2 - N3;
            float4 v = *reinterpret_cast<const float4*>(Wgate + 4 * j);
            do_split4(v, g_wgH, g_wgM, (size_t)j * 4);
        }
    }
}

// ================= main fused kernel =================
__global__ __launch_bounds__(256, 2)
void gser_cp(const float* __restrict__ prev,
             const float* __restrict__ leakp,
             const float* __restrict__ thrp,
             float* __restrict__ out)
{
    const int bx = blockIdx.x;
    const int m0 = blockIdx.y * 128;
    const int n0 = bx * 64;
    const int tid = threadIdx.x;
    const int wid = tid >> 5;
    const int lane = tid & 31;
    const int m0A = (wid & 3) * 32;       // phase A warp grid 4m x 2n (32x32 tiles)
    const int n0A = (wid >> 2) * 32;
    const int n0B = (wid >> 2) * 16;      // phase B warp grid 4m x 2n (32x16 tiles)

    extern __shared__ char smc[];
    const uint32_t sb = smem_u32(smc);
    float* s_lk = reinterpret_cast<float*>(smc + LK_OFF);
    float* s_th = reinterpret_cast<float*>(smc + TH_OFF);

    // zero-fill pad: out[m0:m0+128, 512+bx*64 : +64)
    {
        const float4 z4 = make_float4(0.f, 0.f, 0.f, 0.f);
        #pragma unroll
        for (int it = 0; it < 8; ++it) {
            int idx = tid + 256 * it;
            int r = idx >> 4, q = idx & 15;
            *reinterpret_cast<float4*>(out + (size_t)(m0 + r) * MAXD + ACT + bx * 64 + 4 * q) = z4;
        }
    }
    if (tid < 64) {
        s_lk[tid] = 1.0f / (1.0f + expf(-leakp[n0 + tid]));
        s_th[tid] = log1pf(expf(thrp[n0 + tid]));
    }

    // ldsm lane-address pieces (R7-verified)
    const uint32_t aOffA = (uint32_t)((m0A + (lane & 15)) * 144) + ((lane >> 4) << 4);
    const uint32_t bTr   = (uint32_t)(((lane & 7) + ((lane >> 3) & 1) * 8) * 144)
                         + (uint32_t)((n0A + ((lane >> 4) << 3)) * 2);
    const uint32_t bWn   = (uint32_t)((n0A + (lane & 7) + ((lane >> 4) << 3)) * 144)
                         + ((lane & 8) ? 16u : 0u);
    const uint32_t aOffB = (uint32_t)((m0A + (lane & 15)) * 80) + ((lane >> 4) << 4);
    const uint32_t bGt   = (uint32_t)((n0B + (lane & 7) + ((lane >> 4) << 3)) * 80)
                         + ((lane & 8) ? 16u : 0u);

    // ---------------- cp.async issue lambdas ----------------
    auto issueA = [&](int c, int b) {
        const bool res = (c < 8);
        const int kc = res ? 64 * c : 64 * (c - 8);
        const __half* aH = res ? g_prevH : g_inH;
        const __half* aM = res ? g_prevM : g_inM;
        const int astr = res ? ACT : IN_DIM;
        #pragma unroll
        for (int i = 0; i < 8; ++i) {
            int idx = tid + 256 * i;                 // 0..2047
            int p = idx >> 10, r = (idx >> 3) & 127, q = idx & 7;
            const __half* s = (p ? aM : aH) + (size_t)(m0 + r) * astr + kc + 8 * q;
            CP16(sb + PA_A(b, p) + r * 144 + q * 16, s);
        }
        if (res) {
            #pragma unroll
            for (int i = 0; i < 4; ++i) {
                int idx = tid + 256 * i;             // 0..1023
                int p = idx >> 9, r = (idx >> 3) & 63, q = idx & 7;
                const __half* s = (p ? g_wresM : g_wresH) + (size_t)(kc + r) * ACT + n0 + 8 * q;
                CP16(sb + PA_W(b, p) + r * 144 + q * 16, s);
            }
        } else {
            #pragma unroll
            for (int i = 0; i < 4; ++i) {
                int idx = tid + 256 * i;
                int p = idx >> 9, r = (idx >> 3) & 63, q = idx & 7;
                const __half* s = (p ? g_winM : g_winH) + (size_t)(n0 + r) * IN_DIM + kc + 8 * q;
                CP16(sb + PA_W(b, p) + r * 144 + q * 16, s);
            }
        }
    };
    auto issueB = [&](int cb, int b) {
        const int h = cb >> 2, kc = 32 * (cb & 3);
        #pragma unroll
        for (int i = 0; i < 4; ++i) {
            int idx = tid + 256 * i;                 // 0..1023
            int p = idx >> 9, r = (idx >> 2) & 127, q = idx & 3;
            const __half* s = (p ? g_inM : g_inH) + (size_t)(m0 + r) * IN_DIM + kc + 8 * q;
            CP16(sb + PB_INP(b, p) + r * 80 + q * 16, s);
        }
        #pragma unroll
        for (int i = 0; i < 3; ++i) {
            int idx = tid + 256 * i;                 // 0..767
            int mp = idx >> 7, r = (idx >> 2) & 31, q = idx & 3;
            int mt = mp >> 1, p = mp & 1;
            const __half* s = (p ? g_wgM : g_wgH) + (size_t)(mt * ACT + n0 + 32 * h + r) * IN_DIM + kc + 8 * q;
            CP16(sb + PB_W(b, mt, p) + r * 80 + q * 16, s);
        }
    };

    // ================= Phase A: z = prev@Wres + inputs@Win^T =================
    float z[2][4][4];
    #pragma unroll
    for (int a = 0; a < 2; ++a)
        #pragma unroll
        for (int b = 0; b < 4; ++b)
            #pragma unroll
            for (int k = 0; k < 4; ++k) z[a][b][k] = 0.f;

    auto computeA = [&](int c, int b) {
        const bool tr = (c < 8);
        #pragma unroll
        for (int ks = 0; ks < 4; ++ks) {
            uint32_t aF[2][2][4];
            #pragma unroll
            for (int p = 0; p < 2; ++p) {
                ldsm4(aF[p][0], sb + PA_A(b, p) + aOffA + ks * 32);
                ldsm4(aF[p][1], sb + PA_A(b, p) + aOffA + 16 * 144 + ks * 32);
            }
            uint32_t bF[2][2][4];
            if (tr) {
                #pragma unroll
                for (int p = 0; p < 2; ++p)
                    #pragma unroll
                    for (int j = 0; j < 2; ++j)
                        ldsm4t(bF[p][j], sb + PA_W(b, p) + bTr + (uint32_t)(ks * 16 * 144) + j * 32);
            } else {
                #pragma unroll
                for (int p = 0; p < 2; ++p)
                    #pragma unroll
                    for (int j = 0; j < 2; ++j)
                        ldsm4(bF[p][j], sb + PA_W(b, p) + bWn + (uint32_t)(j * 16 * 144) + ks * 32);
            }
            #pragma unroll
            for (int mi = 0; mi < 2; ++mi)
                #pragma unroll
                for (int j = 0; j < 2; ++j) {
                    three(z[mi][2 * j],     aF[0][mi], aF[1][mi],
                          bF[0][j][0], bF[0][j][1], bF[1][j][0], bF[1][j][1]);
                    three(z[mi][2 * j + 1], aF[0][mi], aF[1][mi],
                          bF[0][j][2], bF[0][j][3], bF[1][j][2], bF[1][j][3]);
                }
        }
    };

    issueA(0, 0); CP_COMMIT();
    issueA(1, 1); CP_COMMIT();
    for (int c = 0; c < 10; ++c) {
        CP_WAIT1();
        __syncthreads();
        computeA(c, c & 1);
        __syncthreads();
        if (c < 8)      { issueA(c + 2, c & 1); CP_COMMIT(); }
        else if (c == 8){ issueB(0, 0);         CP_COMMIT(); }
    }
    issueB(1, 1); CP_COMMIT();

    // ---- park z to out gmem (overwritten by epilogue) ----
    {
        const int tq = lane >> 2, tr2 = lane & 3;
        #pragma unroll
        for (int mi = 0; mi < 2; ++mi) {
            const int r0 = m0A + mi * 16 + tq;
            #pragma unroll
            for (int j = 0; j < 4; ++j) {
                const int cc = n0A + j * 8 + 2 * tr2;
                *reinterpret_cast<float2*>(out + (size_t)(m0 + r0) * MAXD + n0 + cc)
                    = make_float2(z[mi][j][0], z[mi][j][1]);
                *reinterpret_cast<float2*>(out + (size_t)(m0 + r0 + 8) * MAXD + n0 + cc)
                    = make_float2(z[mi][j][2], z[mi][j][3]);
            }
        }
    }
    __syncthreads();

    // ================= Phase B: gates (3 mats), 8 chunks of k=32 =================
    float g[3][2][2][4];
    #pragma unroll
    for (int a = 0; a < 3; ++a)
        #pragma unroll
        for (int b = 0; b < 2; ++b)
            #pragma unroll
            for (int j = 0; j < 2; ++j)
                #pragma unroll
                for (int k = 0; k < 4; ++k) g[a][b][j][k] = 0.f;

    auto computeB = [&](int b) {
        #pragma unroll
        for (int ks = 0; ks < 2; ++ks) {
            uint32_t aF[2][2][4];
            #pragma unroll
            for (int p = 0; p < 2; ++p) {
                ldsm4(aF[p][0], sb + PB_INP(b, p) + aOffB + ks * 32);
                ldsm4(aF[p][1], sb + PB_INP(b, p) + aOffB + 16 * 80 + ks * 32);
            }
            #pragma unroll
            for (int mt = 0; mt < 3; ++mt) {
                uint32_t bF[2][4];
                #pragma unroll
                for (int p = 0; p < 2; ++p)
                    ldsm4(bF[p], sb + PB_W(b, mt, p) + bGt + ks * 32);
                #pragma unroll
                for (int mi = 0; mi < 2; ++mi) {
                    three(g[mt][mi][0], aF[0][mi], aF[1][mi], bF[0][0], bF[0][1], bF[1][0], bF[1][1]);
                    three(g[mt][mi][1], aF[0][mi], aF[1][mi], bF[0][2], bF[0][3], bF[1][2], bF[1][3]);
                }
            }
        }
    };
    auto epilogue = [&](int h) {
        const int tq = lane >> 2, tr2 = lane & 3;
        #pragma unroll
        for (int mi = 0; mi < 2; ++mi) {
            const int rr0 = m0A + mi * 16 + tq;
            const int mg0 = m0 + rr0;
            const int mg1 = mg0 + 8;
            #pragma unroll
            for (int ni = 0; ni < 2; ++ni) {
                const int cc = 32 * h + n0B + ni * 8 + 2 * tr2;
                const int ng = n0 + cc;
                const float lk0 = s_lk[cc], lk1 = s_lk[cc + 1];
                const float th0 = s_th[cc], th1 = s_th[cc + 1];
                const float2 z0 = *reinterpret_cast<const float2*>(out + (size_t)mg0 * MAXD + ng);
                const float2 z1 = *reinterpret_cast<const float2*>(out + (size_t)mg1 * MAXD + ng);
                const float2 p0 = *reinterpret_cast<const float2*>(prev + (size_t)mg0 * MAXD + ng);
                const float2 p1 = *reinterpret_cast<const float2*>(prev + (size_t)mg1 * MAXD + ng);
                float2 o0, o1;
                o0.x = epi(z0.x, g[0][mi][ni][0], g[1][mi][ni][0], g[2][mi][ni][0], p0.x, lk0, th0);
                o0.y = epi(z0.y, g[0][mi][ni][1], g[1][mi][ni][1], g[2][mi][ni][1], p0.y, lk1, th1);
                o1.x = epi(z1.x, g[0][mi][ni][2], g[1][mi][ni][2], g[2][mi][ni][2], p1.x, lk0, th0);
                o1.y = epi(z1.y, g[0][mi][ni][3], g[1][mi][ni][3], g[2][mi][ni][3], p1.y, lk1, th1);
                *reinterpret_cast<float2*>(out + (size_t)mg0 * MAXD + ng) = o0;
                *reinterpret_cast<float2*>(out + (size_t)mg1 * MAXD + ng) = o1;
            }
        }
        #pragma unroll
        for (int a = 0; a < 3; ++a)
            #pragma unroll
            for (int b = 0; b < 2; ++b)
                #pragma unroll
                for (int j = 0; j < 2; ++j)
                    #pragma unroll
                    for (int k = 0; k < 4; ++k) g[a][b][j][k] = 0.f;
    };

    for (int cb = 0; cb < 8; ++cb) {
        if (cb < 7) CP_WAIT1(); else CP_WAIT0();
        __syncthreads();
        computeB(cb & 1);
        if (cb == 3) epilogue(0);
        __syncthreads();
        if (cb < 6) { issueB(cb + 2, cb & 1); CP_COMMIT(); }
    }
    epilogue(1);
}

extern "C" void kernel_launch(void* const* d_in, const int* in_sizes, int n_in,
                              void* d_out, int out_size)
{
    const float* inputs = (const float*)d_in[0];
    const float* prev   = (const float*)d_in[1];
    const float* Wres   = (const float*)d_in[2];
    const float* Win    = (const float*)d_in[3];
    const float* Wgate  = (const float*)d_in[4];
    const float* leakp  = (const float*)d_in[5];
    const float* thrp   = (const float*)d_in[6];
    float* out = (float*)d_out;

    split_all<<<4096, 256>>>(inputs, prev, Wres, Win, Wgate);

    cudaFuncSetAttribute(gser_cp, cudaFuncAttributeMaxDynamicSharedMemorySize, SMEM_BYTES);
    dim3 grid(8, B_SZ / 128);
    gser_cp<<<grid, 256, SMEM_BYTES>>>(prev, leakp, thrp, out);
}

// round 10
// speedup vs baseline: 1.1303x; 1.1303x over previous
#include <cuda_runtime.h>
#include <cuda_fp16.h>
#include <cstdint>

#define B_SZ   32768
#define IN_DIM 128
#define ACT    512
#define MAXD   1024

// ---- smem byte offsets (64-row CTA tiles, single buffered) ----
// Phase A: A tile [64m][64k fp16 stride 144B] x2 pieces; W tile [64][144B] x2 pieces
#define PA_A(p)    ((p)*9216)              // 0, 9216
#define PA_W(p)    (18432 + (p)*9216)      // 18432, 27648 -> end 36864
// Phase B (unions with PA region): inputs [64m][32k stride 80B] x2p; gate W 3x2x[32][80B]
#define PB_INP(p)  ((p)*5120)
#define PB_W(mt,p) (10240 + ((mt)*2+(p))*2560)   // end 25600
#define Z_OFF   36864                      // fp32 [64][stride 72 floats] = 18432B
#define LK_OFF  55296
#define TH_OFF  55552
#define SMEM_BYTES 55808                   // x4 CTAs = 223232B <= 228KB/SM

__device__ __forceinline__ void ldsm4(uint32_t r[4], uint32_t a) {
    asm volatile("ldmatrix.sync.aligned.m8n8.x4.shared.b16 {%0,%1,%2,%3}, [%4];"
        : "=r"(r[0]), "=r"(r[1]), "=r"(r[2]), "=r"(r[3]) : "r"(a));
}
__device__ __forceinline__ void ldsm4t(uint32_t r[4], uint32_t a) {
    asm volatile("ldmatrix.sync.aligned.m8n8.x4.trans.shared.b16 {%0,%1,%2,%3}, [%4];"
        : "=r"(r[0]), "=r"(r[1]), "=r"(r[2]), "=r"(r[3]) : "r"(a));
}
__device__ __forceinline__ uint32_t smem_u32(const void* p) {
    uint32_t a;
    asm("{ .reg .u64 t; cvta.to.shared.u64 t, %1; cvt.u32.u64 %0, t; }" : "=r"(a) : "l"(p));
    return a;
}
__device__ __forceinline__ void mma16(float c[4], const uint32_t a[4], uint32_t b0, uint32_t b1) {
    asm volatile("mma.sync.aligned.m16n8k16.row.col.f32.f16.f16.f32 "
        "{%0,%1,%2,%3},{%4,%5,%6,%7},{%8,%9},{%0,%1,%2,%3};"
        : "+f"(c[0]), "+f"(c[1]), "+f"(c[2]), "+f"(c[3])
        : "r"(a[0]), "r"(a[1]), "r"(a[2]), "r"(a[3]), "r"(b0), "r"(b1));
}
__device__ __forceinline__ uint32_t packh2(float lo, float hi) {
    uint32_t r;
    asm("cvt.rn.f16x2.f32 %0, %1, %2;" : "=r"(r) : "f"(hi), "f"(lo));
    return r;
}
__device__ __forceinline__ float2 unph2(uint32_t p) {
    __half2 h;
    *reinterpret_cast<uint32_t*>(&h) = p;
    return __half22float2(h);
}
__device__ __forceinline__ void split_pair(float x0, float x1, uint32_t& ph, uint32_t& pm) {
    ph = packh2(x0, x1);
    float2 h = unph2(ph);
    pm = packh2(x0 - h.x, x1 - h.y);
}
__device__ __forceinline__ void three(float c[4],
                                      const uint32_t ah[4], const uint32_t am[4],
                                      uint32_t bh0, uint32_t bh1, uint32_t bm0, uint32_t bm1) {
    mma16(c, ah, bh0, bh1);
    mma16(c, ah, bm0, bm1);
    mma16(c, am, bh0, bh1);
}
__device__ __forceinline__ float epi(float z, float gi_, float gf_, float go_,
                                     float p, float lk, float th) {
    float ig = 1.0f / (1.0f + expf(-gi_));
    float fg = 1.0f / (1.0f + expf(-gf_));
    float og = 1.0f / (1.0f + expf(-go_));
    float s = (1.0f - lk) * (fg * p) + lk * tanhf(ig * z);
    s *= og;
    return (s > th) ? (s - th) : s;
}

__global__ __launch_bounds__(128, 4)
void gser_c4(const float* __restrict__ inputs,
             const float* __restrict__ prev,
             const float* __restrict__ Wres,
             const float* __restrict__ Win,
             const float* __restrict__ Wgate,
             const float* __restrict__ leakp,
             const float* __restrict__ thrp,
             float* __restrict__ out)
{
    const int bx = blockIdx.x;
    const int m0 = blockIdx.y * 64;
    const int n0 = bx * 64;
    const int tid = threadIdx.x;
    const int wid = tid >> 5;                 // 0..3
    const int lane = tid & 31;
    const int m0A = (wid & 1) * 32;           // phase A warp grid 2m x 2n (32x32 tiles)
    const int n0A = (wid >> 1) * 32;
    const int n0B = (wid >> 1) * 16;          // phase B warp grid 2m x 2n (32x16 tiles)

    extern __shared__ char smc[];
    const uint32_t sb = smem_u32(smc);
    float* s_lk = reinterpret_cast<float*>(smc + LK_OFF);
    float* s_th = reinterpret_cast<float*>(smc + TH_OFF);
    float* s_z  = reinterpret_cast<float*>(smc + Z_OFF);

    // zero-fill pad: out[m0:m0+64, 512+bx*64 : +64)
    {
        const float4 z4 = make_float4(0.f, 0.f, 0.f, 0.f);
        #pragma unroll
        for (int it = 0; it < 8; ++it) {
            int idx = tid + 128 * it;          // 0..1023
            int r = idx >> 4, q = idx & 15;
            *reinterpret_cast<float4*>(out + (size_t)(m0 + r) * MAXD + ACT + bx * 64 + 4 * q) = z4;
        }
    }
    if (tid < 64) {
        s_lk[tid] = 1.0f / (1.0f + expf(-leakp[n0 + tid]));
        s_th[tid] = log1pf(expf(thrp[n0 + tid]));
    }

    // ldsm lane-address pieces (verified in R7)
    const uint32_t aOffA = (uint32_t)((m0A + (lane & 15)) * 144) + ((lane >> 4) << 4);
    const uint32_t bTr   = (uint32_t)(((lane & 7) + ((lane >> 3) & 1) * 8) * 144)
                         + (uint32_t)((n0A + ((lane >> 4) << 3)) * 2);
    const uint32_t bWn   = (uint32_t)((n0A + (lane & 7) + ((lane >> 4) << 3)) * 144)
                         + ((lane & 8) ? 16u : 0u);
    const uint32_t aOffB = (uint32_t)((m0A + (lane & 15)) * 80) + ((lane >> 4) << 4);
    const uint32_t bGt   = (uint32_t)((n0B + (lane & 7) + ((lane >> 4) << 3)) * 80)
                         + ((lane & 8) ? 16u : 0u);

    // ================= Phase A: z = prev@Wres + inputs@Win^T (32x32 warp tiles) =====
    float z[2][4][4];
    #pragma unroll
    for (int a = 0; a < 2; ++a)
        #pragma unroll
        for (int b = 0; b < 4; ++b)
            #pragma unroll
            for (int k = 0; k < 4; ++k) z[a][b][k] = 0.f;

    for (int c = 0; c < 10; ++c) {
        __syncthreads();
        if (c < 8) {
            const int kc = 64 * c;
            // prev tile [64m][64k]
            #pragma unroll
            for (int it = 0; it < 16; ++it) {
                int idx = tid + 128 * it;      // 0..2047
                int r = idx >> 5, q = idx & 31;
                float2 v = *reinterpret_cast<const float2*>(prev + (size_t)(m0 + r) * MAXD + kc + 2 * q);
                uint32_t ph, pm;
                split_pair(v.x, v.y, ph, pm);
                *reinterpret_cast<uint32_t*>(smc + PA_A(0) + r * 144 + 4 * q) = ph;
                *reinterpret_cast<uint32_t*>(smc + PA_A(1) + r * 144 + 4 * q) = pm;
            }
            // wres tile [64k][64n]
            #pragma unroll
            for (int it = 0; it < 16; ++it) {
                int idx = tid + 128 * it;
                int r = idx >> 5, q = idx & 31;
                float2 w = *reinterpret_cast<const float2*>(Wres + (size_t)(kc + r) * MAXD + n0 + 2 * q);
                uint32_t ph, pm;
                split_pair(w.x, w.y, ph, pm);
                *reinterpret_cast<uint32_t*>(smc + PA_W(0) + r * 144 + 4 * q) = ph;
                *reinterpret_cast<uint32_t*>(smc + PA_W(1) + r * 144 + 4 * q) = pm;
            }
        } else {
            const int kc = 64 * (c - 8);
            // inputs tile [64m][64k]
            #pragma unroll
            for (int it = 0; it < 16; ++it) {
                int idx = tid + 128 * it;
                int r = idx >> 5, q = idx & 31;
                float2 v = *reinterpret_cast<const float2*>(inputs + (size_t)(m0 + r) * IN_DIM + kc + 2 * q);
                uint32_t ph, pm;
                split_pair(v.x, v.y, ph, pm);
                *reinterpret_cast<uint32_t*>(smc + PA_A(0) + r * 144 + 4 * q) = ph;
                *reinterpret_cast<uint32_t*>(smc + PA_A(1) + r * 144 + 4 * q) = pm;
            }
            // Win tile [64n][64k]
            #pragma unroll
            for (int it = 0; it < 16; ++it) {
                int idx = tid + 128 * it;
                int r = idx >> 5, q = idx & 31;
                float2 w = *reinterpret_cast<const float2*>(Win + (size_t)(n0 + r) * IN_DIM + kc + 2 * q);
                uint32_t ph, pm;
                split_pair(w.x, w.y, ph, pm);
                *reinterpret_cast<uint32_t*>(smc + PA_W(0) + r * 144 + 4 * q) = ph;
                *reinterpret_cast<uint32_t*>(smc + PA_W(1) + r * 144 + 4 * q) = pm;
            }
        }
        __syncthreads();

        const bool tr = (c < 8);
        #pragma unroll
        for (int ks = 0; ks < 4; ++ks) {
            uint32_t aF[2][2][4];
            #pragma unroll
            for (int p = 0; p < 2; ++p) {
                ldsm4(aF[p][0], sb + PA_A(p) + aOffA + ks * 32);
                ldsm4(aF[p][1], sb + PA_A(p) + aOffA + 16 * 144 + ks * 32);
            }
            uint32_t bF[2][2][4];
            if (tr) {
                #pragma unroll
                for (int p = 0; p < 2; ++p)
                    #pragma unroll
                    for (int j = 0; j < 2; ++j)
                        ldsm4t(bF[p][j], sb + PA_W(p) + bTr + (uint32_t)(ks * 16 * 144) + j * 32);
            } else {
                #pragma unroll
                for (int p = 0; p < 2; ++p)
                    #pragma unroll
                    for (int j = 0; j < 2; ++j)
                        ldsm4(bF[p][j], sb + PA_W(p) + bWn + (uint32_t)(j * 16 * 144) + ks * 32);
            }
            #pragma unroll
            for (int mi = 0; mi < 2; ++mi)
                #pragma unroll
                for (int j = 0; j < 2; ++j) {
                    three(z[mi][2 * j],     aF[0][mi], aF[1][mi],
                          bF[0][j][0], bF[0][j][1], bF[1][j][0], bF[1][j][1]);
                    three(z[mi][2 * j + 1], aF[0][mi], aF[1][mi],
                          bF[0][j][2], bF[0][j][3], bF[1][j][2], bF[1][j][3]);
                }
        }
    }

    // ---- park z to smem [64][72 floats] ----
    {
        const int tq = lane >> 2, tr2 = lane & 3;
        #pragma unroll
        for (int mi = 0; mi < 2; ++mi) {
            const int r0 = m0A + mi * 16 + tq;
            #pragma unroll
            for (int j = 0; j < 4; ++j) {
                const int cc = n0A + j * 8 + 2 * tr2;
                *reinterpret_cast<float2*>(s_z + (size_t)r0 * 72 + cc)       = make_float2(z[mi][j][0], z[mi][j][1]);
                *reinterpret_cast<float2*>(s_z + (size_t)(r0 + 8) * 72 + cc) = make_float2(z[mi][j][2], z[mi][j][3]);
            }
        }
    }

    // ================= Phase B: gates (3 mats), two 32-col halves =================
    for (int h = 0; h < 2; ++h) {
        float g[3][2][2][4];
        #pragma unroll
        for (int a = 0; a < 3; ++a)
            #pragma unroll
            for (int b = 0; b < 2; ++b)
                #pragma unroll
                for (int j = 0; j < 2; ++j)
                    #pragma unroll
                    for (int k = 0; k < 4; ++k) g[a][b][j][k] = 0.f;

        for (int c = 0; c < 4; ++c) {
            const int kc = 32 * c;
            __syncthreads();
            // inputs [64m][32k]
            #pragma unroll
            for (int it = 0; it < 4; ++it) {
                int idx = tid + 128 * it;          // 0..511
                int r = idx >> 3, q = idx & 7;
                float4 v = *reinterpret_cast<const float4*>(inputs + (size_t)(m0 + r) * IN_DIM + kc + 4 * q);
                uint32_t h0, mm0, h1, mm1;
                split_pair(v.x, v.y, h0, mm0);
                split_pair(v.z, v.w, h1, mm1);
                *reinterpret_cast<uint2*>(smc + PB_INP(0) + r * 80 + q * 8) = make_uint2(h0, h1);
                *reinterpret_cast<uint2*>(smc + PB_INP(1) + r * 80 + q * 8) = make_uint2(mm0, mm1);
            }
            // weights: 3 mats [32n][32k]
            #pragma unroll
            for (int mt = 0; mt < 3; ++mt)
                #pragma unroll
                for (int it = 0; it < 2; ++it) {
                    int idx = tid + 128 * it;      // 0..255
                    int r = idx >> 3, q = idx & 7;
                    const float* W = Wgate + (size_t)(mt * ACT + n0 + 32 * h + r) * IN_DIM + kc + 4 * q;
                    float4 w = *reinterpret_cast<const float4*>(W);
                    uint32_t h0, mm0, h1, mm1;
                    split_pair(w.x, w.y, h0, mm0);
                    split_pair(w.z, w.w, h1, mm1);
                    *reinterpret_cast<uint2*>(smc + PB_W(mt, 0) + r * 80 + q * 8) = make_uint2(h0, h1);
                    *reinterpret_cast<uint2*>(smc + PB_W(mt, 1) + r * 80 + q * 8) = make_uint2(mm0, mm1);
                }
            __syncthreads();

            #pragma unroll
            for (int ks = 0; ks < 2; ++ks) {
                uint32_t aF[2][2][4];
                #pragma unroll
                for (int p = 0; p < 2; ++p) {
                    ldsm4(aF[p][0], sb + PB_INP(p) + aOffB + ks * 32);
                    ldsm4(aF[p][1], sb + PB_INP(p) + aOffB + 16 * 80 + ks * 32);
                }
                #pragma unroll
                for (int mt = 0; mt < 3; ++mt) {
                    uint32_t bF[2][4];
                    #pragma unroll
                    for (int p = 0; p < 2; ++p)
                        ldsm4(bF[p], sb + PB_W(mt, p) + bGt + ks * 32);
                    #pragma unroll
                    for (int mi = 0; mi < 2; ++mi) {
                        three(g[mt][mi][0], aF[0][mi], aF[1][mi], bF[0][0], bF[0][1], bF[1][0], bF[1][1]);
                        three(g[mt][mi][1], aF[0][mi], aF[1][mi], bF[0][2], bF[0][3], bF[1][2], bF[1][3]);
                    }
                }
            }
        }

        // ---- epilogue for this half ----
        const int tq = lane >> 2, tr2 = lane & 3;
        #pragma unroll
        for (int mi = 0; mi < 2; ++mi) {
            const int rr0 = m0A + mi * 16 + tq;
            const int mg0 = m0 + rr0;
            const int mg1 = mg0 + 8;
            #pragma unroll
            for (int ni = 0; ni < 2; ++ni) {
                const int cc = 32 * h + n0B + ni * 8 + 2 * tr2;
                const int ng = n0 + cc;
                const float lk0 = s_lk[cc], lk1 = s_lk[cc + 1];
                const float th0 = s_th[cc], th1 = s_th[cc + 1];
                const float2 z0 = *reinterpret_cast<const float2*>(s_z + (size_t)rr0 * 72 + cc);
                const float2 z1 = *reinterpret_cast<const float2*>(s_z + (size_t)(rr0 + 8) * 72 + cc);
                const float2 p0 = *reinterpret_cast<const float2*>(prev + (size_t)mg0 * MAXD + ng);
                const float2 p1 = *reinterpret_cast<const float2*>(prev + (size_t)mg1 * MAXD + ng);
                float2 o0, o1;
                o0.x = epi(z0.x, g[0][mi][ni][0], g[1][mi][ni][0], g[2][mi][ni][0], p0.x, lk0, th0);
                o0.y = epi(z0.y, g[0][mi][ni][1], g[1][mi][ni][1], g[2][mi][ni][1], p0.y, lk1, th1);
                o1.x = epi(z1.x, g[0][mi][ni][2], g[1][mi][ni][2], g[2][mi][ni][2], p1.x, lk0, th0);
                o1.y = epi(z1.y, g[0][mi][ni][3], g[1][mi][ni][3], g[2][mi][ni][3], p1.y, lk1, th1);
                *reinterpret_cast<float2*>(out + (size_t)mg0 * MAXD + ng) = o0;
                *reinterpret_cast<float2*>(out + (size_t)mg1 * MAXD + ng) = o1;
            }
        }
    }
}

extern "C" void kernel_launch(void* const* d_in, const int* in_sizes, int n_in,
                              void* d_out, int out_size)
{
    const float* inputs = (const float*)d_in[0];
    const float* prev   = (const float*)d_in[1];
    const float* Wres   = (const float*)d_in[2];
    const float* Win    = (const float*)d_in[3];
    const float* Wgate  = (const float*)d_in[4];
    const float* leakp  = (const float*)d_in[5];
    const float* thrp   = (const float*)d_in[6];
    float* out = (float*)d_out;

    cudaFuncSetAttribute(gser_c4, cudaFuncAttributeMaxDynamicSharedMemorySize, SMEM_BYTES);

    dim3 grid(8, B_SZ / 64);
    gser_c4<<<grid, 128, SMEM_BYTES>>>(inputs, prev, Wres, Win, Wgate, leakp, thrp, out);
}

// round 11
// speedup vs baseline: 1.1504x; 1.0178x over previous
#include <cuda_runtime.h>
#include <cuda_fp16.h>
#include <cstdint>

#define B_SZ   32768
#define IN_DIM 128
#define ACT    512
#define MAXD   1024

// ---------------- device-global pre-split arrays (h + m fp16 pieces) ----------------
__device__ __half g_prevH[(size_t)B_SZ * ACT];
__device__ __half g_prevM[(size_t)B_SZ * ACT];
__device__ __half g_inH[(size_t)B_SZ * IN_DIM];
__device__ __half g_inM[(size_t)B_SZ * IN_DIM];
__device__ __half g_wresH[ACT * ACT];      // TRANSPOSED: [n][k]
__device__ __half g_wresM[ACT * ACT];
__device__ __half g_winH[ACT * IN_DIM];    // [n][k] (native)
__device__ __half g_winM[ACT * IN_DIM];
__device__ __half g_wgH[3 * ACT * IN_DIM]; // [n][k] (native)
__device__ __half g_wgM[3 * ACT * IN_DIM];

// ---- smem byte offsets (64x64 CTA tile, single-buffered, occ 4) ----
#define PA_A(p)    ((p)*9216)              // A tile [64m][64k fp16 stride 144B]
#define PA_W(p)    (18432 + (p)*9216)      // W tile [64n][64k fp16 stride 144B]
#define PB_INP(p)  ((p)*5120)              // inputs [64m][32k stride 80B]
#define PB_W(mt,p) (10240 + ((mt)*2+(p))*2560)  // gate W [32n][32k stride 80B]
#define Z_OFF   36864                      // fp32 [64][stride 72 floats]
#define LK_OFF  55296
#define TH_OFF  55552
#define SMEM_BYTES 55808                   // x4 CTAs = 223232 <= 228KB

__device__ __forceinline__ void ldsm4(uint32_t r[4], uint32_t a) {
    asm volatile("ldmatrix.sync.aligned.m8n8.x4.shared.b16 {%0,%1,%2,%3}, [%4];"
        : "=r"(r[0]), "=r"(r[1]), "=r"(r[2]), "=r"(r[3]) : "r"(a));
}
__device__ __forceinline__ uint32_t smem_u32(const void* p) {
    uint32_t a;
    asm("{ .reg .u64 t; cvta.to.shared.u64 t, %1; cvt.u32.u64 %0, t; }" : "=r"(a) : "l"(p));
    return a;
}
__device__ __forceinline__ void mma16(float c[4], const uint32_t a[4], uint32_t b0, uint32_t b1) {
    asm volatile("mma.sync.aligned.m16n8k16.row.col.f32.f16.f16.f32 "
        "{%0,%1,%2,%3},{%4,%5,%6,%7},{%8,%9},{%0,%1,%2,%3};"
        : "+f"(c[0]), "+f"(c[1]), "+f"(c[2]), "+f"(c[3])
        : "r"(a[0]), "r"(a[1]), "r"(a[2]), "r"(a[3]), "r"(b0), "r"(b1));
}
__device__ __forceinline__ void three(float c[4],
                                      const uint32_t ah[4], const uint32_t am[4],
                                      uint32_t bh0, uint32_t bh1, uint32_t bm0, uint32_t bm1) {
    mma16(c, ah, bh0, bh1);
    mma16(c, ah, bm0, bm1);
    mma16(c, am, bh0, bh1);
}
#define CP16(dst, src) asm volatile("cp.async.cg.shared.global [%0], [%1], 16;" :: "r"(dst), "l"(src))
#define CP_COMMIT()    asm volatile("cp.async.commit_group;" ::: "memory")
#define CP_WAIT0()     asm volatile("cp.async.wait_group 0;" ::: "memory")

__device__ __forceinline__ float epi(float z, float gi_, float gf_, float go_,
                                     float p, float lk, float th) {
    float ig = 1.0f / (1.0f + expf(-gi_));
    float fg = 1.0f / (1.0f + expf(-gf_));
    float og = 1.0f / (1.0f + expf(-go_));
    float s = (1.0f - lk) * (fg * p) + lk * tanhf(ig * z);
    s *= og;
    return (s > th) ? (s - th) : s;
}

// ================= preprocess: split fp32 -> (h,m) fp16 pieces =================
__device__ __forceinline__ void do_split4(float4 v, __half* dh, __half* dm, size_t o) {
    __half h0 = __float2half_rn(v.x), h1 = __float2half_rn(v.y);
    __half h2 = __float2half_rn(v.z), h3 = __float2half_rn(v.w);
    __half m0 = __float2half_rn(v.x - __half2float(h0));
    __half m1 = __float2half_rn(v.y - __half2float(h1));
    __half m2 = __float2half_rn(v.z - __half2float(h2));
    __half m3 = __float2half_rn(v.w - __half2float(h3));
    __half2 H0 = __halves2half2(h0, h1), H1 = __halves2half2(h2, h3);
    __half2 M0 = __halves2half2(m0, m1), M1 = __halves2half2(m2, m3);
    uint2 ph, pm;
    ph.x = *reinterpret_cast<uint32_t*>(&H0); ph.y = *reinterpret_cast<uint32_t*>(&H1);
    pm.x = *reinterpret_cast<uint32_t*>(&M0); pm.y = *reinterpret_cast<uint32_t*>(&M1);
    *reinterpret_cast<uint2*>(dh + o) = ph;
    *reinterpret_cast<uint2*>(dm + o) = pm;
}

#define N0 (B_SZ * (ACT/4))        // prev f4 chunks
#define N1 (B_SZ * (IN_DIM/4))     // inputs
#define N2 (ACT * ACT)             // wres transpose (scalar)
#define N3 (ACT * (IN_DIM/4))      // win
#define N4 (3*ACT * (IN_DIM/4))    // wgate
#define NT (N0+N1+N2+N3+N4)

__global__ void split_all(const float* __restrict__ inputs, const float* __restrict__ prev,
                          const float* __restrict__ Wres, const float* __restrict__ Win,
                          const float* __restrict__ Wgate)
{
    for (long i = blockIdx.x * (long)blockDim.x + threadIdx.x; i < NT; i += (long)gridDim.x * blockDim.x) {
        if (i < N0) {
            long r = i >> 7, q = i & 127;
            float4 v = *reinterpret_cast<const float4*>(prev + r * MAXD + 4 * q);
            do_split4(v, g_prevH, g_prevM, (size_t)i * 4);
        } else if (i < N0 + N1) {
            long j = i - N0;
            float4 v = *reinterpret_cast<const float4*>(inputs + 4 * j);
            do_split4(v, g_inH, g_inM, (size_t)j * 4);
        } else if (i < N0 + N1 + N2) {
            long j = i - N0 - N1;            // out linear [n][k]: k fast
            long n = j >> 9, k = j & 511;
            float v = Wres[k * MAXD + n];    // transpose read
            __half h = __float2half_rn(v);
            __half m = __float2half_rn(v - __half2float(h));
            g_wresH[j] = h;
            g_wresM[j] = m;
        } else if (i < N0 + N1 + N2 + N3) {
            long j = i - N0 - N1 - N2;
            float4 v = *reinterpret_cast<const float4*>(Win + 4 * j);
            do_split4(v, g_winH, g_winM, (size_t)j * 4);
        } else {
            long j = i - N0 - N1 - N2 - N3;
            float4 v = *reinterpret_cast<const float4*>(Wgate + 4 * j);
            do_split4(v, g_wgH, g_wgM, (size_t)j * 4);
        }
    }
}

// ================= main fused kernel (128 thr, 4 CTAs/SM) =================
__global__ __launch_bounds__(128, 4)
void gser_v4(const float* __restrict__ prev,
             const float* __restrict__ leakp,
             const float* __restrict__ thrp,
             float* __restrict__ out)
{
    const int bx = blockIdx.x;
    const int m0 = blockIdx.y * 64;
    const int n0 = bx * 64;
    const int tid = threadIdx.x;
    const int wid = tid >> 5;
    const int lane = tid & 31;
    const int m0A = (wid & 1) * 32;           // phase A warp grid 2m x 2n (32x32)
    const int n0A = (wid >> 1) * 32;
    const int n0B = (wid >> 1) * 16;          // phase B warp grid 2m x 2n (32x16)

    extern __shared__ char smc[];
    const uint32_t sb = smem_u32(smc);
    float* s_lk = reinterpret_cast<float*>(smc + LK_OFF);
    float* s_th = reinterpret_cast<float*>(smc + TH_OFF);
    float* s_z  = reinterpret_cast<float*>(smc + Z_OFF);

    // zero-fill pad: out[m0:m0+64, 512+bx*64 : +64)
    {
        const float4 z4 = make_float4(0.f, 0.f, 0.f, 0.f);
        #pragma unroll
        for (int it = 0; it < 8; ++it) {
            int idx = tid + 128 * it;
            int r = idx >> 4, q = idx & 15;
            *reinterpret_cast<float4*>(out + (size_t)(m0 + r) * MAXD + ACT + bx * 64 + 4 * q) = z4;
        }
    }
    if (tid < 64) {
        s_lk[tid] = 1.0f / (1.0f + expf(-leakp[n0 + tid]));
        s_th[tid] = log1pf(expf(thrp[n0 + tid]));
    }

    // ldsm lane-address pieces (R7/R10-verified)
    const uint32_t aOffA = (uint32_t)((m0A + (lane & 15)) * 144) + ((lane >> 4) << 4);
    const uint32_t bWn   = (uint32_t)((n0A + (lane & 7) + ((lane >> 4) << 3)) * 144)
                         + ((lane & 8) ? 16u : 0u);
    const uint32_t aOffB = (uint32_t)((m0A + (lane & 15)) * 80) + ((lane >> 4) << 4);
    const uint32_t bGt   = (uint32_t)((n0B + (lane & 7) + ((lane >> 4) << 3)) * 80)
                         + ((lane & 8) ? 16u : 0u);

    // ================= Phase A: z = prev@Wres + inputs@Win^T =================
    float z[2][4][4];
    #pragma unroll
    for (int a = 0; a < 2; ++a)
        #pragma unroll
        for (int b = 0; b < 4; ++b)
            #pragma unroll
            for (int k = 0; k < 4; ++k) z[a][b][k] = 0.f;

    for (int c = 0; c < 10; ++c) {
        __syncthreads();
        // issue cp.async for this chunk
        if (c < 8) {
            const int kc = 64 * c;
            #pragma unroll
            for (int it = 0; it < 8; ++it) {            // A: 1024 cp16
                int idx = tid + 128 * it;
                int p = idx >> 9, r = (idx >> 3) & 63, q = idx & 7;
                const __half* s = (p ? g_prevM : g_prevH) + (size_t)(m0 + r) * ACT + kc + 8 * q;
                CP16(sb + PA_A(p) + r * 144 + q * 16, s);
            }
            #pragma unroll
            for (int it = 0; it < 8; ++it) {            // W (transposed wres [n][k])
                int idx = tid + 128 * it;
                int p = idx >> 9, r = (idx >> 3) & 63, q = idx & 7;
                const __half* s = (p ? g_wresM : g_wresH) + (size_t)(n0 + r) * ACT + kc + 8 * q;
                CP16(sb + PA_W(p) + r * 144 + q * 16, s);
            }
        } else {
            const int kc = 64 * (c - 8);
            #pragma unroll
            for (int it = 0; it < 8; ++it) {            // A: inputs
                int idx = tid + 128 * it;
                int p = idx >> 9, r = (idx >> 3) & 63, q = idx & 7;
                const __half* s = (p ? g_inM : g_inH) + (size_t)(m0 + r) * IN_DIM + kc + 8 * q;
                CP16(sb + PA_A(p) + r * 144 + q * 16, s);
            }
            #pragma unroll
            for (int it = 0; it < 8; ++it) {            // W: win [n][k]
                int idx = tid + 128 * it;
                int p = idx >> 9, r = (idx >> 3) & 63, q = idx & 7;
                const __half* s = (p ? g_winM : g_winH) + (size_t)(n0 + r) * IN_DIM + kc + 8 * q;
                CP16(sb + PA_W(p) + r * 144 + q * 16, s);
            }
        }
        CP_COMMIT();
        CP_WAIT0();
        __syncthreads();

        #pragma unroll
        for (int ks = 0; ks < 4; ++ks) {
            uint32_t aF[2][2][4];
            #pragma unroll
            for (int p = 0; p < 2; ++p) {
                ldsm4(aF[p][0], sb + PA_A(p) + aOffA + ks * 32);
                ldsm4(aF[p][1], sb + PA_A(p) + aOffA + 16 * 144 + ks * 32);
            }
            uint32_t bF[2][2][4];
            #pragma unroll
            for (int p = 0; p < 2; ++p)
                #pragma unroll
                for (int j = 0; j < 2; ++j)
                    ldsm4(bF[p][j], sb + PA_W(p) + bWn + (uint32_t)(j * 16 * 144) + ks * 32);
            #pragma unroll
            for (int mi = 0; mi < 2; ++mi)
                #pragma unroll
                for (int j = 0; j < 2; ++j) {
                    three(z[mi][2 * j],     aF[0][mi], aF[1][mi],
                          bF[0][j][0], bF[0][j][1], bF[1][j][0], bF[1][j][1]);
                    three(z[mi][2 * j + 1], aF[0][mi], aF[1][mi],
                          bF[0][j][2], bF[0][j][3], bF[1][j][2], bF[1][j][3]);
                }
        }
    }

    // ---- park z to smem [64][72 floats] ----
    {
        const int tq = lane >> 2, tr2 = lane & 3;
        #pragma unroll
        for (int mi = 0; mi < 2; ++mi) {
            const int r0 = m0A + mi * 16 + tq;
            #pragma unroll
            for (int j = 0; j < 4; ++j) {
                const int cc = n0A + j * 8 + 2 * tr2;
                *reinterpret_cast<float2*>(s_z + (size_t)r0 * 72 + cc)       = make_float2(z[mi][j][0], z[mi][j][1]);
                *reinterpret_cast<float2*>(s_z + (size_t)(r0 + 8) * 72 + cc) = make_float2(z[mi][j][2], z[mi][j][3]);
            }
        }
    }

    // ================= Phase B: gates (3 mats), two 32-col halves =================
    for (int h = 0; h < 2; ++h) {
        float g[3][2][2][4];
        #pragma unroll
        for (int a = 0; a < 3; ++a)
            #pragma unroll
            for (int b = 0; b < 2; ++b)
                #pragma unroll
                for (int j = 0; j < 2; ++j)
                    #pragma unroll
                    for (int k = 0; k < 4; ++k) g[a][b][j][k] = 0.f;

        for (int c = 0; c < 4; ++c) {
            const int kc = 32 * c;
            __syncthreads();
            #pragma unroll
            for (int it = 0; it < 4; ++it) {            // inputs: 512 cp16
                int idx = tid + 128 * it;
                int p = idx >> 8, r = (idx >> 2) & 63, q = idx & 3;
                const __half* s = (p ? g_inM : g_inH) + (size_t)(m0 + r) * IN_DIM + kc + 8 * q;
                CP16(sb + PB_INP(p) + r * 80 + q * 16, s);
            }
            #pragma unroll
            for (int it = 0; it < 6; ++it) {            // gate weights: 768 cp16
                int idx = tid + 128 * it;
                int mtp = idx >> 7, r = (idx >> 2) & 31, q = idx & 3;
                int mt = mtp >> 1, p = mtp & 1;
                const __half* s = (p ? g_wgM : g_wgH)
                    + (size_t)(mt * ACT + n0 + 32 * h + r) * IN_DIM + kc + 8 * q;
                CP16(sb + PB_W(mt, p) + r * 80 + q * 16, s);
            }
            CP_COMMIT();
            CP_WAIT0();
            __syncthreads();

            #pragma unroll
            for (int ks = 0; ks < 2; ++ks) {
                uint32_t aF[2][2][4];
                #pragma unroll
                for (int p = 0; p < 2; ++p) {
                    ldsm4(aF[p][0], sb + PB_INP(p) + aOffB + ks * 32);
                    ldsm4(aF[p][1], sb + PB_INP(p) + aOffB + 16 * 80 + ks * 32);
                }
                #pragma unroll
                for (int mt = 0; mt < 3; ++mt) {
                    uint32_t bF[2][4];
                    #pragma unroll
                    for (int p = 0; p < 2; ++p)
                        ldsm4(bF[p], sb + PB_W(mt, p) + bGt + ks * 32);
                    #pragma unroll
                    for (int mi = 0; mi < 2; ++mi) {
                        three(g[mt][mi][0], aF[0][mi], aF[1][mi], bF[0][0], bF[0][1], bF[1][0], bF[1][1]);
                        three(g[mt][mi][1], aF[0][mi], aF[1][mi], bF[0][2], bF[0][3], bF[1][2], bF[1][3]);
                    }
                }
            }
        }

        // ---- epilogue for this half ----
        const int tq = lane >> 2, tr2 = lane & 3;
        #pragma unroll
        for (int mi = 0; mi < 2; ++mi) {
            const int rr0 = m0A + mi * 16 + tq;
            const int mg0 = m0 + rr0;
            const int mg1 = mg0 + 8;
            #pragma unroll
            for (int ni = 0; ni < 2; ++ni) {
                const int cc = 32 * h + n0B + ni * 8 + 2 * tr2;
                const int ng = n0 + cc;
                const float lk0 = s_lk[cc], lk1 = s_lk[cc + 1];
                const float th0 = s_th[cc], th1 = s_th[cc + 1];
                const float2 z0 = *reinterpret_cast<const float2*>(s_z + (size_t)rr0 * 72 + cc);
                const float2 z1 = *reinterpret_cast<const float2*>(s_z + (size_t)(rr0 + 8) * 72 + cc);
                const float2 p0 = *reinterpret_cast<const float2*>(prev + (size_t)mg0 * MAXD + ng);
                const float2 p1 = *reinterpret_cast<const float2*>(prev + (size_t)mg1 * MAXD + ng);
                float2 o0, o1;
                o0.x = epi(z0.x, g[0][mi][ni][0], g[1][mi][ni][0], g[2][mi][ni][0], p0.x, lk0, th0);
                o0.y = epi(z0.y, g[0][mi][ni][1], g[1][mi][ni][1], g[2][mi][ni][1], p0.y, lk1, th1);
                o1.x = epi(z1.x, g[0][mi][ni][2], g[1][mi][ni][2], g[2][mi][ni][2], p1.x, lk0, th0);
                o1.y = epi(z1.y, g[0][mi][ni][3], g[1][mi][ni][3], g[2][mi][ni][3], p1.y, lk1, th1);
                *reinterpret_cast<float2*>(out + (size_t)mg0 * MAXD + ng) = o0;
                *reinterpret_cast<float2*>(out + (size_t)mg1 * MAXD + ng) = o1;
            }
        }
    }
}

extern "C" void kernel_launch(void* const* d_in, const int* in_sizes, int n_in,
                              void* d_out, int out_size)
{
    const float* inputs = (const float*)d_in[0];
    const float* prev   = (const float*)d_in[1];
    const float* Wres   = (const float*)d_in[2];
    const float* Win    = (const float*)d_in[3];
    const float* Wgate  = (const float*)d_in[4];
    const float* leakp  = (const float*)d_in[5];
    const float* thrp   = (const float*)d_in[6];
    float* out = (float*)d_out;

    split_all<<<4096, 256>>>(inputs, prev, Wres, Win, Wgate);

    cudaFuncSetAttribute(gser_v4, cudaFuncAttributeMaxDynamicSharedMemorySize, SMEM_BYTES);
    dim3 grid(8, B_SZ / 64);
    gser_v4<<<grid, 128, SMEM_BYTES>>>(prev, leakp, thrp, out);
}